// round 11
// baseline (speedup 1.0000x reference)
#include <cuda_runtime.h>
#include <cuda_fp16.h>
#include <math.h>
#include <cstdint>

#define B_ 64
#define T_ 256
#define C_ 384
#define H_ 6
#define D_ 64
#define K_ 384
#define M_TOT (B_*T_)   // 16384
#define KP2 (K_/2)      // 192 u32 (half2) per row

// ------------------------- scratch (no allocation) -------------------------
__device__ uint32_t g_xh[M_TOT*KP2];        // x, fp16 pairs, pair-slotted
__device__ uint32_t g_wqh[3*C_*KP2];        // Wqkv^T [n][pair-slot(k)]
__device__ uint32_t g_wph[C_*KP2];          // Wproj^T
__device__ uint32_t g_atth[M_TOT*KP2];      // attention out, fp16 slotted
__device__ uint32_t g_qh[B_*H_*T_*(D_/2)];  // [b,h,t][d-pair slot]
__device__ uint32_t g_kh[B_*H_*T_*(D_/2)];
__device__ uint32_t g_vh[B_*H_*T_*(D_/2)];
__device__ uint32_t g_vt[B_*H_*D_*(T_/2)];  // V^T: [b,h,d][key-pair slot]

// ------------------------- helpers -------------------------
__device__ __forceinline__ int slot8(int p) { return (p & ~7) | (((p & 3) << 1) | ((p >> 2) & 1)); }
__device__ __forceinline__ int inv8(int s)  { return ((s & 1) << 2) | ((s >> 1) & 3); }

__device__ __forceinline__ uint32_t pack2f(float a, float b) {
    __half2 h = __floats2half2_rn(a, b);
    return *reinterpret_cast<uint32_t*>(&h);
}
__device__ __forceinline__ uint32_t pack2h(__half a, __half b) {
    __half2 h = __halves2half2(a, b);
    return *reinterpret_cast<uint32_t*>(&h);
}
__device__ __forceinline__ void mma_f16(float c[4], const uint32_t a[4], uint32_t b0, uint32_t b1) {
    asm volatile(
        "mma.sync.aligned.m16n8k16.row.col.f32.f16.f16.f32 "
        "{%0,%1,%2,%3}, {%4,%5,%6,%7}, {%8,%9}, {%0,%1,%2,%3};"
        : "+f"(c[0]), "+f"(c[1]), "+f"(c[2]), "+f"(c[3])
        : "r"(a[0]), "r"(a[1]), "r"(a[2]), "r"(a[3]), "r"(b0), "r"(b1));
}
#define CP16(dst, src) asm volatile("cp.async.cg.shared.global [%0], [%1], 16;" :: "r"(dst), "l"(src) : "memory")
#define CP_COMMIT()    asm volatile("cp.async.commit_group;" ::: "memory")
#define CP_WAIT1()     asm volatile("cp.async.wait_group 1;" ::: "memory")
#define CP_WAIT0()     asm volatile("cp.async.wait_group 0;" ::: "memory")
__device__ __forceinline__ uint32_t smem_u32(const void* p) {
    uint32_t a;
    asm("{ .reg .u64 t; cvta.to.shared.u64 t, %1; cvt.u32.u64 %0, t; }" : "=r"(a) : "l"(p));
    return a;
}

// ------------------------- conversion kernels -------------------------
__global__ __launch_bounds__(256) void conv_x(const float* __restrict__ x) {
    const int gi = blockIdx.x * 256 + threadIdx.x;
    const float* s = x + (size_t)gi * 16;
    float4 v0 = *(const float4*)(s);
    float4 v1 = *(const float4*)(s + 4);
    float4 v2 = *(const float4*)(s + 8);
    float4 v3 = *(const float4*)(s + 12);
    uint32_t* o = g_xh + (size_t)gi * 8;
    o[0] = pack2f(v0.x, v0.y); o[2] = pack2f(v0.z, v0.w);
    o[4] = pack2f(v1.x, v1.y); o[6] = pack2f(v1.z, v1.w);
    o[1] = pack2f(v2.x, v2.y); o[3] = pack2f(v2.z, v2.w);
    o[5] = pack2f(v3.x, v3.y); o[7] = pack2f(v3.z, v3.w);
}

template<int WHICH>
__global__ void conv_w(const float* __restrict__ W, int N) {
    __shared__ float t[32][33];
    uint32_t* out = (WHICH == 0) ? g_wqh : g_wph;
    const int nx = blockIdx.x * 32, kx = blockIdx.y * 32;
    const int x = threadIdx.x, y = threadIdx.y;
    #pragma unroll
    for (int i = y; i < 32; i += 8) t[i][x] = W[(size_t)(kx + i) * N + nx + x];
    __syncthreads();
    #pragma unroll
    for (int i = y; i < 16; i += 8) {
        const int slot = slot8(i);
        out[(size_t)(nx + x) * KP2 + kx / 2 + slot] = pack2f(t[2 * i][x], t[2 * i + 1][x]);
    }
}

__global__ __launch_bounds__(256) void conv_v() {
    __shared__ uint32_t sm[64][33];
    const int bh = blockIdx.x >> 2, kt = blockIdx.x & 3;
    const int tid = threadIdx.x;
    const uint32_t* src = g_vh + (size_t)(bh * T_ + kt * 64) * 32;
    #pragma unroll
    for (int j = 0; j < 8; j++) {
        const int u = tid + j * 256;
        sm[u >> 5][u & 31] = src[(u >> 5) * 32 + (u & 31)];
    }
    __syncthreads();
    #pragma unroll
    for (int j = 0; j < 8; j++) {
        const int u = tid + j * 256;
        const int d = u >> 5, kidx = u & 31;
        const int kp = (kidx & 24) | inv8(kidx & 7);
        const int pd = d >> 1;
        const int s = slot8(pd);
        __half2 a = *reinterpret_cast<__half2*>(&sm[2 * kp][s]);
        __half2 b = *reinterpret_cast<__half2*>(&sm[2 * kp + 1][s]);
        uint32_t val = (d & 1) ? pack2h(__high2half(a), __high2half(b))
                               : pack2h(__low2half(a), __low2half(b));
        g_vt[((size_t)bh * 64 + d) * (T_ / 2) + kt * 32 + kidx] = val;
    }
}

// ---------------------------------------------------------------------------
// fp16 MMA GEMM (unchanged from round-10 passing kernel).
// Block 128(M)x64(N), BK=32, 256 threads, 8 warps 4x2, warp tile 32x32.
// ---------------------------------------------------------------------------
#define GP 24
#define STG (192 * GP * 4)       // 18432 B/stage
#define GEMM_SMEM (3 * STG)      // 55296

template<int N, int MODE>
__global__ __launch_bounds__(256, 3) void gemm_h(const float* __restrict__ bias,
                                                 float* __restrict__ out) {
    extern __shared__ char smem[];
    const uint32_t sb = smem_u32(smem);
    const uint32_t* sm = (const uint32_t*)smem;

    const int tid = threadIdx.x;
    const int wid = tid >> 5;
    const int lane = tid & 31;
    const int r = lane >> 2, q = lane & 3;
    const int m0 = blockIdx.y * 128;
    const int n0 = blockIdx.x * 64;
    const int wm = (wid & 3) * 32;
    const int wn = (wid >> 2) * 32;

    const uint32_t* Ap = (MODE == 0) ? g_xh : g_atth;
    const uint32_t* Bp = (MODE == 0) ? g_wqh : g_wph;

    auto load_stage = [&](int kc, int st) {
        #pragma unroll
        for (int j = 0; j < 3; j++) {
            const int c = tid + j * 256;
            const int row = c >> 2, seg = c & 3;
            const uint32_t* src = (row < 128)
                ? Ap + (size_t)(m0 + row) * KP2 + kc * 16 + seg * 4
                : Bp + (size_t)(n0 + row - 128) * KP2 + kc * 16 + seg * 4;
            CP16(sb + st * STG + row * (GP * 4) + seg * 16, src);
        }
        CP_COMMIT();
    };

    float acc[2][4][4] = {};
    load_stage(0, 0);
    load_stage(1, 1);

    const int NCH = K_ / 32;   // 12
    for (int kc = 0; kc < NCH; kc++) {
        const int st = kc % 3;
        if (kc < NCH - 1) CP_WAIT1(); else CP_WAIT0();
        __syncthreads();
        if (kc + 2 < NCH) load_stage(kc + 2, (kc + 2) % 3);

        const uint32_t* As = sm + st * (STG / 4);
        const uint32_t* Bs = As + 128 * GP;
        #pragma unroll
        for (int ks = 0; ks < 2; ks++) {
            const int koff = ks * 8 + 2 * q;
            uint32_t af[2][4];
            #pragma unroll
            for (int mt = 0; mt < 2; mt++) {
                const int mr = wm + mt * 16 + r;
                uint2 a0 = *(const uint2*)&As[mr * GP + koff];
                uint2 a1 = *(const uint2*)&As[(mr + 8) * GP + koff];
                af[mt][0] = a0.x; af[mt][1] = a1.x; af[mt][2] = a0.y; af[mt][3] = a1.y;
            }
            uint2 bf[4];
            #pragma unroll
            for (int nt = 0; nt < 4; nt++)
                bf[nt] = *(const uint2*)&Bs[(wn + nt * 8 + r) * GP + koff];
            #pragma unroll
            for (int mt = 0; mt < 2; mt++)
                #pragma unroll
                for (int nt = 0; nt < 4; nt++)
                    mma_f16(acc[mt][nt], af[mt], bf[nt].x, bf[nt].y);
        }
    }

    // ---- epilogue ----
    #pragma unroll
    for (int mt = 0; mt < 2; mt++) {
        #pragma unroll
        for (int nt = 0; nt < 4; nt++) {
            const int row0 = m0 + wm + mt * 16 + r;
            const int row1 = row0 + 8;
            const int col = n0 + wn + nt * 8 + q * 2;
            const float b0 = bias[col], b1 = bias[col + 1];
            const float v00 = acc[mt][nt][0] + b0, v01 = acc[mt][nt][1] + b1;
            const float v10 = acc[mt][nt][2] + b0, v11 = acc[mt][nt][3] + b1;
            if (MODE == 0) {
                const int which = n0 / C_;
                const int rem = col - which * C_;
                const int h = rem >> 6, d = rem & 63;
                const int slot = slot8(d >> 1);
                uint32_t* qkv = (which == 0) ? g_qh : (which == 1) ? g_kh : g_vh;
                const int b0i = row0 >> 8, t0 = row0 & 255;
                const int b1i = row1 >> 8, t1 = row1 & 255;
                qkv[((size_t)(b0i * H_ + h) * T_ + t0) * 32 + slot] = pack2f(v00, v01);
                qkv[((size_t)(b1i * H_ + h) * T_ + t1) * 32 + slot] = pack2f(v10, v11);
            } else {
                *(float2*)&out[(size_t)row0 * N + col] = make_float2(v00, v01);
                *(float2*)&out[(size_t)row1 * N + col] = make_float2(v10, v11);
            }
        }
    }
}

// ---------------------------------------------------------------------------
// Flash attention, fp16 mma. Br=128, Bc=64, 256 threads (8 warps x 16 rows).
// Double-buffered K/V cp.async (overlap load jt+1 with compute jt).
// Causal warp-skip on fully-masked tiles. grid=(T/128, B*H).
// smem (u32, pitch 40): Q[128] @0, P[128] @5120, K[2][64] @10240, V[2][64] @15360
// ---------------------------------------------------------------------------
#define AP 40
#define ATT_SMEM 81920

__global__ __launch_bounds__(256) void attn_h() {
    extern __shared__ uint32_t dsm[];
    uint32_t* Qs = dsm;            // 128 x 40
    uint32_t* Ps = dsm + 5120;     // 128 x 40

    const int tid = threadIdx.x;
    const int w = tid >> 5;
    const int lane = tid & 31;
    const int r = lane >> 2, q = lane & 3;
    const int qt = blockIdx.x;     // 0..1 (128-row q blocks)
    const int bh = blockIdx.y;
    const int wrow = w * 16;

    const uint32_t sbase = smem_u32(dsm);
    const uint32_t sQ = sbase;
    const uint32_t sK = sbase + 40960;
    const uint32_t sV = sbase + 61440;

    // Q tile: 128 rows x 32 u32
    {
        const uint32_t* src = g_qh + (size_t)(bh * T_ + qt * 128) * 32;
        #pragma unroll
        for (int j = 0; j < 4; j++) {
            const int c = tid + j * 256;
            const int row = c >> 3, seg = c & 7;
            CP16(sQ + row * (AP * 4) + seg * 16, src + row * 32 + seg * 4);
        }
        CP_COMMIT();
    }

    auto load_kv = [&](int jt, int buf) {
        const uint32_t* ksrc = g_kh + (size_t)(bh * T_ + jt * 64) * 32;
        const uint32_t* vsrc = g_vt + (size_t)bh * 64 * (T_ / 2) + jt * 32;
        #pragma unroll
        for (int j = 0; j < 2; j++) {
            const int c = tid + j * 256;
            const int row = c >> 3, seg = c & 7;
            CP16(sK + buf * 10240 + row * (AP * 4) + seg * 16, ksrc + row * 32 + seg * 4);
            CP16(sV + buf * 10240 + row * (AP * 4) + seg * 16, vsrc + (size_t)row * (T_ / 2) + seg * 4);
        }
        CP_COMMIT();
    };
    load_kv(0, 0);

    float m0 = -INFINITY, m1 = -INFINITY, l0 = 0.f, l1 = 0.f;
    float Oacc[8][4] = {};

    const int nkt = 2 * (qt + 1);
    for (int jt = 0; jt < nkt; jt++) {
        if (jt + 1 < nkt) load_kv(jt + 1, (jt + 1) & 1);
        if (jt + 1 < nkt) CP_WAIT1(); else CP_WAIT0();
        __syncthreads();

        // warp-skip: all 16 rows of this warp strictly below every key in tile
        if (qt * 128 + wrow + 15 >= jt * 64) {
            const uint32_t* Kb = dsm + 10240 + (jt & 1) * 2560;
            const uint32_t* Vb = dsm + 15360 + (jt & 1) * 2560;

            // ---- S = Q K^T ----
            float S[8][4] = {};
            #pragma unroll
            for (int ks = 0; ks < 4; ks++) {
                const int koff = ks * 8 + 2 * q;
                uint2 a0 = *(const uint2*)&Qs[(wrow + r) * AP + koff];
                uint2 a1 = *(const uint2*)&Qs[(wrow + r + 8) * AP + koff];
                uint32_t af[4] = {a0.x, a1.x, a0.y, a1.y};
                #pragma unroll
                for (int nt = 0; nt < 8; nt++) {
                    uint2 b = *(const uint2*)&Kb[(nt * 8 + r) * AP + koff];
                    mma_f16(S[nt], af, b.x, b.y);
                }
            }

            #pragma unroll
            for (int nt = 0; nt < 8; nt++)
                #pragma unroll
                for (int c = 0; c < 4; c++)
                    S[nt][c] *= 0.125f;

            // causal mask (only when tile straddles/exceeds this warp's rows)
            if (jt * 64 + 63 > qt * 128 + wrow) {
                const int ir0 = qt * 128 + wrow + r;
                const int ir1 = ir0 + 8;
                #pragma unroll
                for (int nt = 0; nt < 8; nt++) {
                    const int jc = jt * 64 + nt * 8 + 2 * q;
                    if (jc > ir0)     S[nt][0] = -INFINITY;
                    if (jc + 1 > ir0) S[nt][1] = -INFINITY;
                    if (jc > ir1)     S[nt][2] = -INFINITY;
                    if (jc + 1 > ir1) S[nt][3] = -INFINITY;
                }
            }

            // ---- online softmax ----
            float mx0 = -INFINITY, mx1 = -INFINITY;
            #pragma unroll
            for (int nt = 0; nt < 8; nt++) {
                mx0 = fmaxf(mx0, fmaxf(S[nt][0], S[nt][1]));
                mx1 = fmaxf(mx1, fmaxf(S[nt][2], S[nt][3]));
            }
            mx0 = fmaxf(mx0, __shfl_xor_sync(0xffffffffu, mx0, 1));
            mx0 = fmaxf(mx0, __shfl_xor_sync(0xffffffffu, mx0, 2));
            mx1 = fmaxf(mx1, __shfl_xor_sync(0xffffffffu, mx1, 1));
            mx1 = fmaxf(mx1, __shfl_xor_sync(0xffffffffu, mx1, 2));
            const float mn0 = fmaxf(m0, mx0), mn1 = fmaxf(m1, mx1);
            const float al0 = __expf(m0 - mn0), al1 = __expf(m1 - mn1);
            float s0 = 0.f, s1 = 0.f;
            #pragma unroll
            for (int nt = 0; nt < 8; nt++) {
                float p0 = __expf(S[nt][0] - mn0);
                float p1 = __expf(S[nt][1] - mn0);
                float p2 = __expf(S[nt][2] - mn1);
                float p3 = __expf(S[nt][3] - mn1);
                s0 += p0 + p1; s1 += p2 + p3;
                const int slot = (nt >> 1) * 8 + (q << 1) + (nt & 1);
                Ps[(wrow + r) * AP + slot] = pack2f(p0, p1);
                Ps[(wrow + r + 8) * AP + slot] = pack2f(p2, p3);
            }
            s0 += __shfl_xor_sync(0xffffffffu, s0, 1);
            s0 += __shfl_xor_sync(0xffffffffu, s0, 2);
            s1 += __shfl_xor_sync(0xffffffffu, s1, 1);
            s1 += __shfl_xor_sync(0xffffffffu, s1, 2);
            l0 = l0 * al0 + s0; l1 = l1 * al1 + s1;
            m0 = mn0; m1 = mn1;
            #pragma unroll
            for (int nt = 0; nt < 8; nt++) {
                Oacc[nt][0] *= al0; Oacc[nt][1] *= al0;
                Oacc[nt][2] *= al1; Oacc[nt][3] *= al1;
            }
            __syncwarp();

            // ---- O += P V ----
            #pragma unroll
            for (int ks = 0; ks < 4; ks++) {
                const int koff = ks * 8 + 2 * q;
                uint2 a0 = *(const uint2*)&Ps[(wrow + r) * AP + koff];
                uint2 a1 = *(const uint2*)&Ps[(wrow + r + 8) * AP + koff];
                uint32_t af[4] = {a0.x, a1.x, a0.y, a1.y};
                #pragma unroll
                for (int nt = 0; nt < 8; nt++) {
                    uint2 b = *(const uint2*)&Vb[(nt * 8 + r) * AP + koff];
                    mma_f16(Oacc[nt], af, b.x, b.y);
                }
            }
        }
        __syncthreads();
    }

    // ---- epilogue: normalize, write g_atth fp16 slotted ----
    const float li0 = 1.f / l0, li1 = 1.f / l1;
    const int b = bh / H_;
    const int h = bh - b * H_;
    const int row0 = qt * 128 + wrow + r;
    const int row1 = row0 + 8;
    uint32_t* o0 = g_atth + (size_t)(b * T_ + row0) * KP2 + h * 32;
    uint32_t* o1 = g_atth + (size_t)(b * T_ + row1) * KP2 + h * 32;
    #pragma unroll
    for (int nt = 0; nt < 8; nt++) {
        const int slot = (nt >> 1) * 8 + (q << 1) + (nt & 1);
        o0[slot] = pack2f(Oacc[nt][0] * li0, Oacc[nt][1] * li0);
        o1[slot] = pack2f(Oacc[nt][2] * li1, Oacc[nt][3] * li1);
    }
}

// ---------------------------------------------------------------------------
extern "C" void kernel_launch(void* const* d_in, const int* in_sizes, int n_in,
                              void* d_out, int out_size) {
    const float* x     = (const float*)d_in[0];
    const float* Wqkv  = (const float*)d_in[1];
    const float* bqkv  = (const float*)d_in[2];
    const float* Wproj = (const float*)d_in[3];
    const float* bproj = (const float*)d_in[4];
    float* out = (float*)d_out;

    cudaFuncSetAttribute(gemm_h<3 * C_, 0>, cudaFuncAttributeMaxDynamicSharedMemorySize, GEMM_SMEM);
    cudaFuncSetAttribute(gemm_h<C_, 1>,     cudaFuncAttributeMaxDynamicSharedMemorySize, GEMM_SMEM);
    cudaFuncSetAttribute(attn_h,            cudaFuncAttributeMaxDynamicSharedMemorySize, ATT_SMEM);

    // 0) fp16 conversions
    conv_x<<<M_TOT * K_ / 16 / 256, 256>>>(x);
    conv_w<0><<<dim3(3 * C_ / 32, K_ / 32), dim3(32, 8)>>>(Wqkv, 3 * C_);
    conv_w<1><<<dim3(C_ / 32, K_ / 32), dim3(32, 8)>>>(Wproj, C_);

    // 1) QKV projection -> fp16 q/k/v
    gemm_h<3 * C_, 0><<<dim3(3 * C_ / 64, M_TOT / 128), 256, GEMM_SMEM>>>(bqkv, nullptr);

    // 1b) V transpose for PV mma
    conv_v<<<B_ * H_ * 4, 256>>>();

    // 2) causal flash attention (fp16 tensor cores, Br=128, pipelined K/V)
    attn_h<<<dim3(T_ / 128, B_ * H_), 256, ATT_SMEM>>>();

    // 3) output projection
    gemm_h<C_, 1><<<dim3(C_ / 64, M_TOT / 128), 256, GEMM_SMEM>>>(bproj, out);
}

// round 12
// speedup vs baseline: 1.0255x; 1.0255x over previous
#include <cuda_runtime.h>
#include <cuda_fp16.h>
#include <math.h>
#include <cstdint>

#define B_ 64
#define T_ 256
#define C_ 384
#define H_ 6
#define D_ 64
#define K_ 384
#define M_TOT (B_*T_)   // 16384
#define KP2 (K_/2)      // 192 u32 (half2) per row

// ------------------------- scratch (no allocation) -------------------------
__device__ uint32_t g_xh[M_TOT*KP2];        // x, fp16 pairs, pair-slotted
__device__ uint32_t g_wqh[3*C_*KP2];        // Wqkv^T [n][pair-slot(k)]
__device__ uint32_t g_wph[C_*KP2];          // Wproj^T
__device__ uint32_t g_atth[M_TOT*KP2];      // attention out, fp16 slotted
__device__ uint32_t g_qh[B_*H_*T_*(D_/2)];  // [b,h,t][d-pair slot]
__device__ uint32_t g_kh[B_*H_*T_*(D_/2)];
__device__ uint32_t g_vh[B_*H_*T_*(D_/2)];
__device__ uint32_t g_vt[B_*H_*D_*(T_/2)];  // V^T: [b,h,d][key-pair slot]

// ------------------------- helpers -------------------------
__device__ __forceinline__ int slot8(int p) { return (p & ~7) | (((p & 3) << 1) | ((p >> 2) & 1)); }
__device__ __forceinline__ int inv8(int s)  { return ((s & 1) << 2) | ((s >> 1) & 3); }

__device__ __forceinline__ uint32_t pack2f(float a, float b) {
    __half2 h = __floats2half2_rn(a, b);
    return *reinterpret_cast<uint32_t*>(&h);
}
__device__ __forceinline__ uint32_t pack2h(__half a, __half b) {
    __half2 h = __halves2half2(a, b);
    return *reinterpret_cast<uint32_t*>(&h);
}
__device__ __forceinline__ void mma_f16(float c[4], const uint32_t a[4], uint32_t b0, uint32_t b1) {
    asm volatile(
        "mma.sync.aligned.m16n8k16.row.col.f32.f16.f16.f32 "
        "{%0,%1,%2,%3}, {%4,%5,%6,%7}, {%8,%9}, {%0,%1,%2,%3};"
        : "+f"(c[0]), "+f"(c[1]), "+f"(c[2]), "+f"(c[3])
        : "r"(a[0]), "r"(a[1]), "r"(a[2]), "r"(a[3]), "r"(b0), "r"(b1));
}
#define CP16(dst, src) asm volatile("cp.async.cg.shared.global [%0], [%1], 16;" :: "r"(dst), "l"(src) : "memory")
#define CP_COMMIT()    asm volatile("cp.async.commit_group;" ::: "memory")
#define CP_WAIT1()     asm volatile("cp.async.wait_group 1;" ::: "memory")
#define CP_WAIT0()     asm volatile("cp.async.wait_group 0;" ::: "memory")
__device__ __forceinline__ uint32_t smem_u32(const void* p) {
    uint32_t a;
    asm("{ .reg .u64 t; cvta.to.shared.u64 t, %1; cvt.u32.u64 %0, t; }" : "=r"(a) : "l"(p));
    return a;
}

// ------------------------- conversion kernels -------------------------
__global__ __launch_bounds__(256) void conv_x(const float* __restrict__ x) {
    const int gi = blockIdx.x * 256 + threadIdx.x;
    const float* s = x + (size_t)gi * 16;
    float4 v0 = *(const float4*)(s);
    float4 v1 = *(const float4*)(s + 4);
    float4 v2 = *(const float4*)(s + 8);
    float4 v3 = *(const float4*)(s + 12);
    uint32_t* o = g_xh + (size_t)gi * 8;
    o[0] = pack2f(v0.x, v0.y); o[2] = pack2f(v0.z, v0.w);
    o[4] = pack2f(v1.x, v1.y); o[6] = pack2f(v1.z, v1.w);
    o[1] = pack2f(v2.x, v2.y); o[3] = pack2f(v2.z, v2.w);
    o[5] = pack2f(v3.x, v3.y); o[7] = pack2f(v3.z, v3.w);
}

// combined W transpose: blocks [0,36) -> Wqkv (N=1152), [36,48) -> Wproj (N=384)
__global__ void conv_w(const float* __restrict__ Wq, const float* __restrict__ Wp) {
    __shared__ float t[32][33];
    const int bx = blockIdx.x;
    const bool isq = bx < 36;
    const float* W = isq ? Wq : Wp;
    uint32_t* out = isq ? g_wqh : g_wph;
    const int N = isq ? 1152 : 384;
    const int nx = (isq ? bx : bx - 36) * 32;
    const int kx = blockIdx.y * 32;
    const int x = threadIdx.x, y = threadIdx.y;
    #pragma unroll
    for (int i = y; i < 32; i += 8) t[i][x] = W[(size_t)(kx + i) * N + nx + x];
    __syncthreads();
    #pragma unroll
    for (int i = y; i < 16; i += 8) {
        const int slot = slot8(i);
        out[(size_t)(nx + x) * KP2 + kx / 2 + slot] = pack2f(t[2 * i][x], t[2 * i + 1][x]);
    }
}

__global__ __launch_bounds__(256) void conv_v() {
    __shared__ uint32_t sm[64][33];
    const int bh = blockIdx.x >> 2, kt = blockIdx.x & 3;
    const int tid = threadIdx.x;
    const uint32_t* src = g_vh + (size_t)(bh * T_ + kt * 64) * 32;
    #pragma unroll
    for (int j = 0; j < 8; j++) {
        const int u = tid + j * 256;
        sm[u >> 5][u & 31] = src[(u >> 5) * 32 + (u & 31)];
    }
    __syncthreads();
    #pragma unroll
    for (int j = 0; j < 8; j++) {
        const int u = tid + j * 256;
        const int d = u >> 5, kidx = u & 31;
        const int kp = (kidx & 24) | inv8(kidx & 7);
        const int pd = d >> 1;
        const int s = slot8(pd);
        __half2 a = *reinterpret_cast<__half2*>(&sm[2 * kp][s]);
        __half2 b = *reinterpret_cast<__half2*>(&sm[2 * kp + 1][s]);
        uint32_t val = (d & 1) ? pack2h(__high2half(a), __high2half(b))
                               : pack2h(__low2half(a), __low2half(b));
        g_vt[((size_t)bh * 64 + d) * (T_ / 2) + kt * 32 + kidx] = val;
    }
}

// ---------------------------------------------------------------------------
// fp16 MMA GEMM. Block 128(M)x64(N), BK=32, 256 threads, 8 warps 4x2,
// warp tile 32x32. Fully-unrolled 12-chunk k-loop (static stage indices).
// ---------------------------------------------------------------------------
#define GP 24
#define STG (192 * GP * 4)       // 18432 B/stage
#define GEMM_SMEM (3 * STG)      // 55296

template<int N, int MODE>
__global__ __launch_bounds__(256, 3) void gemm_h(const float* __restrict__ bias,
                                                 float* __restrict__ out) {
    extern __shared__ char smem[];
    const uint32_t sb = smem_u32(smem);
    const uint32_t* sm = (const uint32_t*)smem;

    const int tid = threadIdx.x;
    const int wid = tid >> 5;
    const int lane = tid & 31;
    const int r = lane >> 2, q = lane & 3;
    const int m0 = blockIdx.y * 128;
    const int n0 = blockIdx.x * 64;
    const int wm = (wid & 3) * 32;
    const int wn = (wid >> 2) * 32;

    const uint32_t* Ap = (MODE == 0) ? g_xh : g_atth;
    const uint32_t* Bp = (MODE == 0) ? g_wqh : g_wph;

    // per-thread source pointers (row/seg fixed across stages)
    const int c0 = tid,        row0l = c0 >> 2, seg0 = c0 & 3;
    const int c1 = tid + 256,  row1l = c1 >> 2, seg1 = c1 & 3;
    const int c2 = tid + 512,  row2l = c2 >> 2, seg2 = c2 & 3;
    const uint32_t* src0 = Ap + (size_t)(m0 + row0l) * KP2 + seg0 * 4;
    const uint32_t* src1 = (row1l < 128)
        ? Ap + (size_t)(m0 + row1l) * KP2 + seg1 * 4
        : Bp + (size_t)(n0 + row1l - 128) * KP2 + seg1 * 4;
    const uint32_t* src2 = Bp + (size_t)(n0 + row2l - 128) * KP2 + seg2 * 4;
    const uint32_t d0 = sb + row0l * (GP * 4) + seg0 * 16;
    const uint32_t d1 = sb + row1l * (GP * 4) + seg1 * 16;
    const uint32_t d2 = sb + row2l * (GP * 4) + seg2 * 16;

    auto load_stage = [&](int kc, int st) {
        const int ko = kc * 16;
        CP16(d0 + st * STG, src0 + ko);
        CP16(d1 + st * STG, src1 + ko);
        CP16(d2 + st * STG, src2 + ko);
        CP_COMMIT();
    };

    float acc[2][4][4] = {};
    load_stage(0, 0);
    load_stage(1, 1);

    const int NCH = K_ / 32;   // 12
    #pragma unroll
    for (int kc = 0; kc < NCH; kc++) {
        const int st = kc % 3;
        if (kc < NCH - 1) CP_WAIT1(); else CP_WAIT0();
        __syncthreads();
        if (kc + 2 < NCH) load_stage(kc + 2, (kc + 2) % 3);

        const uint32_t* As = sm + st * (STG / 4);
        const uint32_t* Bs = As + 128 * GP;
        #pragma unroll
        for (int ks = 0; ks < 2; ks++) {
            const int koff = ks * 8 + 2 * q;
            uint32_t af[2][4];
            #pragma unroll
            for (int mt = 0; mt < 2; mt++) {
                const int mr = wm + mt * 16 + r;
                uint2 a0 = *(const uint2*)&As[mr * GP + koff];
                uint2 a1 = *(const uint2*)&As[(mr + 8) * GP + koff];
                af[mt][0] = a0.x; af[mt][1] = a1.x; af[mt][2] = a0.y; af[mt][3] = a1.y;
            }
            uint2 bf[4];
            #pragma unroll
            for (int nt = 0; nt < 4; nt++)
                bf[nt] = *(const uint2*)&Bs[(wn + nt * 8 + r) * GP + koff];
            #pragma unroll
            for (int mt = 0; mt < 2; mt++)
                #pragma unroll
                for (int nt = 0; nt < 4; nt++)
                    mma_f16(acc[mt][nt], af[mt], bf[nt].x, bf[nt].y);
        }
    }

    // ---- epilogue ----
    #pragma unroll
    for (int mt = 0; mt < 2; mt++) {
        #pragma unroll
        for (int nt = 0; nt < 4; nt++) {
            const int row0 = m0 + wm + mt * 16 + r;
            const int row1 = row0 + 8;
            const int col = n0 + wn + nt * 8 + q * 2;
            const float b0 = bias[col], b1 = bias[col + 1];
            const float v00 = acc[mt][nt][0] + b0, v01 = acc[mt][nt][1] + b1;
            const float v10 = acc[mt][nt][2] + b0, v11 = acc[mt][nt][3] + b1;
            if (MODE == 0) {
                const int which = n0 / C_;
                const int rem = col - which * C_;
                const int h = rem >> 6, d = rem & 63;
                const int slot = slot8(d >> 1);
                uint32_t* qkv = (which == 0) ? g_qh : (which == 1) ? g_kh : g_vh;
                const int b0i = row0 >> 8, t0 = row0 & 255;
                const int b1i = row1 >> 8, t1 = row1 & 255;
                qkv[((size_t)(b0i * H_ + h) * T_ + t0) * 32 + slot] = pack2f(v00, v01);
                qkv[((size_t)(b1i * H_ + h) * T_ + t1) * 32 + slot] = pack2f(v10, v11);
            } else {
                *(float2*)&out[(size_t)row0 * N + col] = make_float2(v00, v01);
                *(float2*)&out[(size_t)row1 * N + col] = make_float2(v10, v11);
            }
        }
    }
}

// ---------------------------------------------------------------------------
// Flash attention, fp16 mma. Br=128, Bc=64, 256 threads (8 warps x 16 rows).
// Double-buffered K/V cp.async; P passes S-MMA C-fragment -> PV A-fragment
// in REGISTERS (no smem round-trip). Causal warp-skip.
// smem (u32, pitch 40): Q[128] @0, K[2][64] @5120, V[2][64] @10240
// ---------------------------------------------------------------------------
#define AP 40
#define ATT_SMEM 61440

__global__ __launch_bounds__(256) void attn_h() {
    extern __shared__ uint32_t dsm[];
    uint32_t* Qs = dsm;            // 128 x 40

    const int tid = threadIdx.x;
    const int w = tid >> 5;
    const int lane = tid & 31;
    const int r = lane >> 2, q = lane & 3;
    const int qt = blockIdx.x;     // 0..1
    const int bh = blockIdx.y;
    const int wrow = w * 16;

    const uint32_t sbase = smem_u32(dsm);
    const uint32_t sQ = sbase;
    const uint32_t sK = sbase + 20480;
    const uint32_t sV = sbase + 40960;

    // Q tile: 128 rows x 32 u32
    {
        const uint32_t* src = g_qh + (size_t)(bh * T_ + qt * 128) * 32;
        #pragma unroll
        for (int j = 0; j < 4; j++) {
            const int c = tid + j * 256;
            const int row = c >> 3, seg = c & 7;
            CP16(sQ + row * (AP * 4) + seg * 16, src + row * 32 + seg * 4);
        }
        CP_COMMIT();
    }

    auto load_kv = [&](int jt, int buf) {
        const uint32_t* ksrc = g_kh + (size_t)(bh * T_ + jt * 64) * 32;
        const uint32_t* vsrc = g_vt + (size_t)bh * 64 * (T_ / 2) + jt * 32;
        #pragma unroll
        for (int j = 0; j < 2; j++) {
            const int c = tid + j * 256;
            const int row = c >> 3, seg = c & 7;
            CP16(sK + buf * 10240 + row * (AP * 4) + seg * 16, ksrc + row * 32 + seg * 4);
            CP16(sV + buf * 10240 + row * (AP * 4) + seg * 16, vsrc + (size_t)row * (T_ / 2) + seg * 4);
        }
        CP_COMMIT();
    };
    load_kv(0, 0);

    float m0 = -INFINITY, m1 = -INFINITY, l0 = 0.f, l1 = 0.f;
    float Oacc[8][4] = {};

    const int nkt = 2 * (qt + 1);
    for (int jt = 0; jt < nkt; jt++) {
        if (jt + 1 < nkt) load_kv(jt + 1, (jt + 1) & 1);
        if (jt + 1 < nkt) CP_WAIT1(); else CP_WAIT0();
        __syncthreads();

        if (qt * 128 + wrow + 15 >= jt * 64) {
            const uint32_t* Kb = dsm + 5120 + (jt & 1) * 2560;
            const uint32_t* Vb = dsm + 10240 + (jt & 1) * 2560;

            // ---- S = Q K^T ----
            float S[8][4] = {};
            #pragma unroll
            for (int ks = 0; ks < 4; ks++) {
                const int koff = ks * 8 + 2 * q;
                uint2 a0 = *(const uint2*)&Qs[(wrow + r) * AP + koff];
                uint2 a1 = *(const uint2*)&Qs[(wrow + r + 8) * AP + koff];
                uint32_t af[4] = {a0.x, a1.x, a0.y, a1.y};
                #pragma unroll
                for (int nt = 0; nt < 8; nt++) {
                    uint2 b = *(const uint2*)&Kb[(nt * 8 + r) * AP + koff];
                    mma_f16(S[nt], af, b.x, b.y);
                }
            }

            #pragma unroll
            for (int nt = 0; nt < 8; nt++)
                #pragma unroll
                for (int c = 0; c < 4; c++)
                    S[nt][c] *= 0.125f;

            if (jt * 64 + 63 > qt * 128 + wrow) {
                const int ir0 = qt * 128 + wrow + r;
                const int ir1 = ir0 + 8;
                #pragma unroll
                for (int nt = 0; nt < 8; nt++) {
                    const int jc = jt * 64 + nt * 8 + 2 * q;
                    if (jc > ir0)     S[nt][0] = -INFINITY;
                    if (jc + 1 > ir0) S[nt][1] = -INFINITY;
                    if (jc > ir1)     S[nt][2] = -INFINITY;
                    if (jc + 1 > ir1) S[nt][3] = -INFINITY;
                }
            }

            // ---- online softmax; P stays in registers as PV A-fragments ----
            float mx0 = -INFINITY, mx1 = -INFINITY;
            #pragma unroll
            for (int nt = 0; nt < 8; nt++) {
                mx0 = fmaxf(mx0, fmaxf(S[nt][0], S[nt][1]));
                mx1 = fmaxf(mx1, fmaxf(S[nt][2], S[nt][3]));
            }
            mx0 = fmaxf(mx0, __shfl_xor_sync(0xffffffffu, mx0, 1));
            mx0 = fmaxf(mx0, __shfl_xor_sync(0xffffffffu, mx0, 2));
            mx1 = fmaxf(mx1, __shfl_xor_sync(0xffffffffu, mx1, 1));
            mx1 = fmaxf(mx1, __shfl_xor_sync(0xffffffffu, mx1, 2));
            const float mn0 = fmaxf(m0, mx0), mn1 = fmaxf(m1, mx1);
            const float al0 = __expf(m0 - mn0), al1 = __expf(m1 - mn1);
            float s0 = 0.f, s1 = 0.f;
            uint32_t Pa[8], Pb[8];   // (row r | row r+8) x cols nt*8+2q,+1
            #pragma unroll
            for (int nt = 0; nt < 8; nt++) {
                float p0 = __expf(S[nt][0] - mn0);
                float p1 = __expf(S[nt][1] - mn0);
                float p2 = __expf(S[nt][2] - mn1);
                float p3 = __expf(S[nt][3] - mn1);
                s0 += p0 + p1; s1 += p2 + p3;
                Pa[nt] = pack2f(p0, p1);
                Pb[nt] = pack2f(p2, p3);
            }
            s0 += __shfl_xor_sync(0xffffffffu, s0, 1);
            s0 += __shfl_xor_sync(0xffffffffu, s0, 2);
            s1 += __shfl_xor_sync(0xffffffffu, s1, 1);
            s1 += __shfl_xor_sync(0xffffffffu, s1, 2);
            l0 = l0 * al0 + s0; l1 = l1 * al1 + s1;
            m0 = mn0; m1 = mn1;
            #pragma unroll
            for (int nt = 0; nt < 8; nt++) {
                Oacc[nt][0] *= al0; Oacc[nt][1] *= al0;
                Oacc[nt][2] *= al1; Oacc[nt][3] *= al1;
            }

            // ---- O += P V (A-fragments direct from registers) ----
            #pragma unroll
            for (int ks = 0; ks < 4; ks++) {
                const int koff = ks * 8 + 2 * q;
                uint32_t af[4] = {Pa[2 * ks], Pb[2 * ks], Pa[2 * ks + 1], Pb[2 * ks + 1]};
                #pragma unroll
                for (int nt = 0; nt < 8; nt++) {
                    uint2 b = *(const uint2*)&Vb[(nt * 8 + r) * AP + koff];
                    mma_f16(Oacc[nt], af, b.x, b.y);
                }
            }
        }
        __syncthreads();
    }

    // ---- epilogue: normalize, write g_atth fp16 slotted ----
    const float li0 = 1.f / l0, li1 = 1.f / l1;
    const int b = bh / H_;
    const int h = bh - b * H_;
    const int row0 = qt * 128 + wrow + r;
    const int row1 = row0 + 8;
    uint32_t* o0 = g_atth + (size_t)(b * T_ + row0) * KP2 + h * 32;
    uint32_t* o1 = g_atth + (size_t)(b * T_ + row1) * KP2 + h * 32;
    #pragma unroll
    for (int nt = 0; nt < 8; nt++) {
        const int slot = (nt >> 1) * 8 + (q << 1) + (nt & 1);
        o0[slot] = pack2f(Oacc[nt][0] * li0, Oacc[nt][1] * li0);
        o1[slot] = pack2f(Oacc[nt][2] * li1, Oacc[nt][3] * li1);
    }
}

// ---------------------------------------------------------------------------
extern "C" void kernel_launch(void* const* d_in, const int* in_sizes, int n_in,
                              void* d_out, int out_size) {
    const float* x     = (const float*)d_in[0];
    const float* Wqkv  = (const float*)d_in[1];
    const float* bqkv  = (const float*)d_in[2];
    const float* Wproj = (const float*)d_in[3];
    const float* bproj = (const float*)d_in[4];
    float* out = (float*)d_out;

    cudaFuncSetAttribute(gemm_h<3 * C_, 0>, cudaFuncAttributeMaxDynamicSharedMemorySize, GEMM_SMEM);
    cudaFuncSetAttribute(gemm_h<C_, 1>,     cudaFuncAttributeMaxDynamicSharedMemorySize, GEMM_SMEM);
    cudaFuncSetAttribute(attn_h,            cudaFuncAttributeMaxDynamicSharedMemorySize, ATT_SMEM);

    // 0) fp16 conversions (conv_w merged: one launch for both weights)
    conv_x<<<M_TOT * K_ / 16 / 256, 256>>>(x);
    conv_w<<<dim3(48, K_ / 32), dim3(32, 8)>>>(Wqkv, Wproj);

    // 1) QKV projection -> fp16 q/k/v
    gemm_h<3 * C_, 0><<<dim3(3 * C_ / 64, M_TOT / 128), 256, GEMM_SMEM>>>(bqkv, nullptr);

    // 1b) V transpose for PV mma
    conv_v<<<B_ * H_ * 4, 256>>>();

    // 2) causal flash attention (fp16 tensor cores, register P)
    attn_h<<<dim3(T_ / 128, B_ * H_), 256, ATT_SMEM>>>();

    // 3) output projection
    gemm_h<C_, 1><<<dim3(C_ / 64, M_TOT / 128), 256, GEMM_SMEM>>>(bproj, out);
}

// round 14
// speedup vs baseline: 1.0883x; 1.0613x over previous
#include <cuda_runtime.h>
#include <cuda_fp16.h>
#include <math.h>
#include <cstdint>

#define B_ 64
#define T_ 256
#define C_ 384
#define H_ 6
#define D_ 64
#define K_ 384
#define M_TOT (B_*T_)   // 16384
#define KP2 (K_/2)      // 192 u32 (half2) per row

// ------------------------- scratch (no allocation) -------------------------
__device__ uint32_t g_xh[M_TOT*KP2];        // x, fp16 pairs, pair-slotted
__device__ uint32_t g_wqh[3*C_*KP2];        // Wqkv^T [n][pair-slot(k)]
__device__ uint32_t g_wph[C_*KP2];          // Wproj^T
__device__ uint32_t g_atth[M_TOT*KP2];      // attention out, fp16 slotted
__device__ uint32_t g_qh[B_*H_*T_*(D_/2)];  // [b,h,t][d-pair slot]
__device__ uint32_t g_kh[B_*H_*T_*(D_/2)];
__device__ uint32_t g_vt[B_*H_*D_*(T_/2)];  // V^T: [b,h,d][key-pair slot]

// ------------------------- helpers -------------------------
__device__ __forceinline__ int slot8(int p) { return (p & ~7) | (((p & 3) << 1) | ((p >> 2) & 1)); }

__device__ __forceinline__ uint32_t pack2f(float a, float b) {
    __half2 h = __floats2half2_rn(a, b);
    return *reinterpret_cast<uint32_t*>(&h);
}
__device__ __forceinline__ void mma_f16(float c[4], const uint32_t a[4], uint32_t b0, uint32_t b1) {
    asm volatile(
        "mma.sync.aligned.m16n8k16.row.col.f32.f16.f16.f32 "
        "{%0,%1,%2,%3}, {%4,%5,%6,%7}, {%8,%9}, {%0,%1,%2,%3};"
        : "+f"(c[0]), "+f"(c[1]), "+f"(c[2]), "+f"(c[3])
        : "r"(a[0]), "r"(a[1]), "r"(a[2]), "r"(a[3]), "r"(b0), "r"(b1));
}
#define CP16(dst, src) asm volatile("cp.async.cg.shared.global [%0], [%1], 16;" :: "r"(dst), "l"(src) : "memory")
#define CP_COMMIT()    asm volatile("cp.async.commit_group;" ::: "memory")
#define CP_WAIT1()     asm volatile("cp.async.wait_group 1;" ::: "memory")
#define CP_WAIT0()     asm volatile("cp.async.wait_group 0;" ::: "memory")
__device__ __forceinline__ uint32_t smem_u32(const void* p) {
    uint32_t a;
    asm("{ .reg .u64 t; cvta.to.shared.u64 t, %1; cvt.u32.u64 %0, t; }" : "=r"(a) : "l"(p));
    return a;
}

// ------------------------- merged conversion kernel -------------------------
// blocks [0,1536): x -> g_xh (16 floats / thread, slotted half2)
// blocks [1536,2112): W transpose -> g_wqh / g_wph
#define CONVX_BLOCKS (M_TOT * K_ / 16 / 256)   // 1536
__global__ __launch_bounds__(256) void conv_in(const float* __restrict__ x,
                                               const float* __restrict__ Wq,
                                               const float* __restrict__ Wp) {
    __shared__ float t[32][33];
    const int bx = blockIdx.x;
    const int tid = threadIdx.x;
    if (bx < CONVX_BLOCKS) {
        const int gi = bx * 256 + tid;
        const float* s = x + (size_t)gi * 16;
        float4 v0 = *(const float4*)(s);
        float4 v1 = *(const float4*)(s + 4);
        float4 v2 = *(const float4*)(s + 8);
        float4 v3 = *(const float4*)(s + 12);
        uint32_t* o = g_xh + (size_t)gi * 8;
        o[0] = pack2f(v0.x, v0.y); o[2] = pack2f(v0.z, v0.w);
        o[4] = pack2f(v1.x, v1.y); o[6] = pack2f(v1.z, v1.w);
        o[1] = pack2f(v2.x, v2.y); o[3] = pack2f(v2.z, v2.w);
        o[5] = pack2f(v3.x, v3.y); o[7] = pack2f(v3.z, v3.w);
    } else {
        const int idx = bx - CONVX_BLOCKS;     // 0..575
        const int wbx = idx % 48;              // n-tile
        const int ky = idx / 48;               // k-tile (0..11)
        const bool isq = wbx < 36;
        const float* W = isq ? Wq : Wp;
        uint32_t* out = isq ? g_wqh : g_wph;
        const int N = isq ? 1152 : 384;
        const int nx = (isq ? wbx : wbx - 36) * 32;
        const int kx = ky * 32;
        const int xi = tid & 31, yi = tid >> 5;
        #pragma unroll
        for (int i = yi; i < 32; i += 8) t[i][xi] = W[(size_t)(kx + i) * N + nx + xi];
        __syncthreads();
        #pragma unroll
        for (int i = yi; i < 16; i += 8) {
            const int slot = slot8(i);
            out[(size_t)(nx + xi) * KP2 + kx / 2 + slot] = pack2f(t[2 * i][xi], t[2 * i + 1][xi]);
        }
    }
}

// ---------------------------------------------------------------------------
// fp16 MMA GEMM. Block 128(M)x64(N), BK=32, 256 threads, 8 warps 4x2,
// warp tile 32x32. Fully-unrolled 12-chunk k-loop.
// MODE 0 epilogue: q/k slotted; V transposed IN-REGISTER (shfl) -> g_vt.
// ---------------------------------------------------------------------------
#define GP 24
#define STG (192 * GP * 4)       // 18432 B/stage
#define GEMM_SMEM (3 * STG)      // 55296

template<int N, int MODE>
__global__ __launch_bounds__(256, 3) void gemm_h(const float* __restrict__ bias,
                                                 float* __restrict__ out) {
    extern __shared__ char smem[];
    const uint32_t sb = smem_u32(smem);
    const uint32_t* sm = (const uint32_t*)smem;

    const int tid = threadIdx.x;
    const int wid = tid >> 5;
    const int lane = tid & 31;
    const int r = lane >> 2, q = lane & 3;
    const int m0 = blockIdx.y * 128;
    const int n0 = blockIdx.x * 64;
    const int wm = (wid & 3) * 32;
    const int wn = (wid >> 2) * 32;

    const uint32_t* Ap = (MODE == 0) ? g_xh : g_atth;
    const uint32_t* Bp = (MODE == 0) ? g_wqh : g_wph;

    const int c0 = tid,        row0l = c0 >> 2, seg0 = c0 & 3;
    const int c1 = tid + 256,  row1l = c1 >> 2, seg1 = c1 & 3;
    const int c2 = tid + 512,  row2l = c2 >> 2, seg2 = c2 & 3;
    const uint32_t* src0 = Ap + (size_t)(m0 + row0l) * KP2 + seg0 * 4;
    const uint32_t* src1 = (row1l < 128)
        ? Ap + (size_t)(m0 + row1l) * KP2 + seg1 * 4
        : Bp + (size_t)(n0 + row1l - 128) * KP2 + seg1 * 4;
    const uint32_t* src2 = Bp + (size_t)(n0 + row2l - 128) * KP2 + seg2 * 4;
    const uint32_t d0 = sb + row0l * (GP * 4) + seg0 * 16;
    const uint32_t d1 = sb + row1l * (GP * 4) + seg1 * 16;
    const uint32_t d2 = sb + row2l * (GP * 4) + seg2 * 16;

    auto load_stage = [&](int kc, int st) {
        const int ko = kc * 16;
        CP16(d0 + st * STG, src0 + ko);
        CP16(d1 + st * STG, src1 + ko);
        CP16(d2 + st * STG, src2 + ko);
        CP_COMMIT();
    };

    float acc[2][4][4] = {};
    load_stage(0, 0);
    load_stage(1, 1);

    const int NCH = K_ / 32;   // 12
    #pragma unroll
    for (int kc = 0; kc < NCH; kc++) {
        const int st = kc % 3;
        if (kc < NCH - 1) CP_WAIT1(); else CP_WAIT0();
        __syncthreads();
        if (kc + 2 < NCH) load_stage(kc + 2, (kc + 2) % 3);

        const uint32_t* As = sm + st * (STG / 4);
        const uint32_t* Bs = As + 128 * GP;
        #pragma unroll
        for (int ks = 0; ks < 2; ks++) {
            const int koff = ks * 8 + 2 * q;
            uint32_t af[2][4];
            #pragma unroll
            for (int mt = 0; mt < 2; mt++) {
                const int mr = wm + mt * 16 + r;
                uint2 a0 = *(const uint2*)&As[mr * GP + koff];
                uint2 a1 = *(const uint2*)&As[(mr + 8) * GP + koff];
                af[mt][0] = a0.x; af[mt][1] = a1.x; af[mt][2] = a0.y; af[mt][3] = a1.y;
            }
            uint2 bf[4];
            #pragma unroll
            for (int nt = 0; nt < 4; nt++)
                bf[nt] = *(const uint2*)&Bs[(wn + nt * 8 + r) * GP + koff];
            #pragma unroll
            for (int mt = 0; mt < 2; mt++)
                #pragma unroll
                for (int nt = 0; nt < 4; nt++)
                    mma_f16(acc[mt][nt], af[mt], bf[nt].x, bf[nt].y);
        }
    }

    // ---- epilogue ----
    #pragma unroll
    for (int mt = 0; mt < 2; mt++) {
        #pragma unroll
        for (int nt = 0; nt < 4; nt++) {
            const int row0 = m0 + wm + mt * 16 + r;
            const int row1 = row0 + 8;
            const int col = n0 + wn + nt * 8 + q * 2;
            const float b0 = bias[col], b1 = bias[col + 1];
            const float v00 = acc[mt][nt][0] + b0, v01 = acc[mt][nt][1] + b1;
            const float v10 = acc[mt][nt][2] + b0, v11 = acc[mt][nt][3] + b1;
            if (MODE == 0) {
                const int which = n0 / C_;
                const int rem = col - which * C_;
                const int h = rem >> 6, d = rem & 63;
                const int b0i = row0 >> 8;
                if (which < 2) {
                    const int slot = slot8(d >> 1);
                    uint32_t* qkv = (which == 0) ? g_qh : g_kh;
                    const int t0 = row0 & 255;
                    const int t1 = row1 & 255;
                    qkv[((size_t)(b0i * H_ + h) * T_ + t0) * 32 + slot] = pack2f(v00, v01);
                    qkv[((size_t)(b0i * H_ + h) * T_ + t1) * 32 + slot] = pack2f(v10, v11);
                } else {
                    // V: in-register transpose via neighbor shuffle (rows r, r^1)
                    const float p00 = __shfl_xor_sync(0xffffffffu, v00, 4);
                    const float p01 = __shfl_xor_sync(0xffffffffu, v01, 4);
                    const float p10 = __shfl_xor_sync(0xffffffffu, v10, 4);
                    const float p11 = __shfl_xor_sync(0xffffffffu, v11, 4);
                    if (!(r & 1)) {
                        const int t0 = row0 & 255;          // even
                        const int t1 = row1 & 255;          // even
                        const int s0 = slot8(t0 >> 1);
                        const int s1 = slot8(t1 >> 1);
                        uint32_t* vt = g_vt + (size_t)(b0i * H_ + h) * 64 * (T_ / 2);
                        vt[(size_t)d * (T_ / 2) + s0]       = pack2f(v00, p00);
                        vt[(size_t)(d + 1) * (T_ / 2) + s0] = pack2f(v01, p01);
                        vt[(size_t)d * (T_ / 2) + s1]       = pack2f(v10, p10);
                        vt[(size_t)(d + 1) * (T_ / 2) + s1] = pack2f(v11, p11);
                    }
                }
            } else {
                *(float2*)&out[(size_t)row0 * N + col] = make_float2(v00, v01);
                *(float2*)&out[(size_t)row1 * N + col] = make_float2(v10, v11);
            }
        }
    }
}

// ---------------------------------------------------------------------------
// Flash attention, fp16 mma (unchanged from round-12 passing kernel).
// Br=128, Bc=64, 256 threads. Double-buffered K/V; register-resident P.
// smem (u32, pitch 40): Q[128] @0, K[2][64] @5120, V[2][64] @10240
// ---------------------------------------------------------------------------
#define AP 40
#define ATT_SMEM 61440

__global__ __launch_bounds__(256) void attn_h() {
    extern __shared__ uint32_t dsm[];
    uint32_t* Qs = dsm;            // 128 x 40

    const int tid = threadIdx.x;
    const int w = tid >> 5;
    const int lane = tid & 31;
    const int r = lane >> 2, q = lane & 3;
    const int qt = blockIdx.x;     // 0..1
    const int bh = blockIdx.y;
    const int wrow = w * 16;

    const uint32_t sbase = smem_u32(dsm);
    const uint32_t sQ = sbase;
    const uint32_t sK = sbase + 20480;
    const uint32_t sV = sbase + 40960;

    {
        const uint32_t* src = g_qh + (size_t)(bh * T_ + qt * 128) * 32;
        #pragma unroll
        for (int j = 0; j < 4; j++) {
            const int c = tid + j * 256;
            const int row = c >> 3, seg = c & 7;
            CP16(sQ + row * (AP * 4) + seg * 16, src + row * 32 + seg * 4);
        }
        CP_COMMIT();
    }

    auto load_kv = [&](int jt, int buf) {
        const uint32_t* ksrc = g_kh + (size_t)(bh * T_ + jt * 64) * 32;
        const uint32_t* vsrc = g_vt + (size_t)bh * 64 * (T_ / 2) + jt * 32;
        #pragma unroll
        for (int j = 0; j < 2; j++) {
            const int c = tid + j * 256;
            const int row = c >> 3, seg = c & 7;
            CP16(sK + buf * 10240 + row * (AP * 4) + seg * 16, ksrc + row * 32 + seg * 4);
            CP16(sV + buf * 10240 + row * (AP * 4) + seg * 16, vsrc + (size_t)row * (T_ / 2) + seg * 4);
        }
        CP_COMMIT();
    };
    load_kv(0, 0);

    float m0 = -INFINITY, m1 = -INFINITY, l0 = 0.f, l1 = 0.f;
    float Oacc[8][4] = {};

    const int nkt = 2 * (qt + 1);
    for (int jt = 0; jt < nkt; jt++) {
        if (jt + 1 < nkt) load_kv(jt + 1, (jt + 1) & 1);
        if (jt + 1 < nkt) CP_WAIT1(); else CP_WAIT0();
        __syncthreads();

        if (qt * 128 + wrow + 15 >= jt * 64) {
            const uint32_t* Kb = dsm + 5120 + (jt & 1) * 2560;
            const uint32_t* Vb = dsm + 10240 + (jt & 1) * 2560;

            float S[8][4] = {};
            #pragma unroll
            for (int ks = 0; ks < 4; ks++) {
                const int koff = ks * 8 + 2 * q;
                uint2 a0 = *(const uint2*)&Qs[(wrow + r) * AP + koff];
                uint2 a1 = *(const uint2*)&Qs[(wrow + r + 8) * AP + koff];
                uint32_t af[4] = {a0.x, a1.x, a0.y, a1.y};
                #pragma unroll
                for (int nt = 0; nt < 8; nt++) {
                    uint2 b = *(const uint2*)&Kb[(nt * 8 + r) * AP + koff];
                    mma_f16(S[nt], af, b.x, b.y);
                }
            }

            #pragma unroll
            for (int nt = 0; nt < 8; nt++)
                #pragma unroll
                for (int c = 0; c < 4; c++)
                    S[nt][c] *= 0.125f;

            if (jt * 64 + 63 > qt * 128 + wrow) {
                const int ir0 = qt * 128 + wrow + r;
                const int ir1 = ir0 + 8;
                #pragma unroll
                for (int nt = 0; nt < 8; nt++) {
                    const int jc = jt * 64 + nt * 8 + 2 * q;
                    if (jc > ir0)     S[nt][0] = -INFINITY;
                    if (jc + 1 > ir0) S[nt][1] = -INFINITY;
                    if (jc > ir1)     S[nt][2] = -INFINITY;
                    if (jc + 1 > ir1) S[nt][3] = -INFINITY;
                }
            }

            float mx0 = -INFINITY, mx1 = -INFINITY;
            #pragma unroll
            for (int nt = 0; nt < 8; nt++) {
                mx0 = fmaxf(mx0, fmaxf(S[nt][0], S[nt][1]));
                mx1 = fmaxf(mx1, fmaxf(S[nt][2], S[nt][3]));
            }
            mx0 = fmaxf(mx0, __shfl_xor_sync(0xffffffffu, mx0, 1));
            mx0 = fmaxf(mx0, __shfl_xor_sync(0xffffffffu, mx0, 2));
            mx1 = fmaxf(mx1, __shfl_xor_sync(0xffffffffu, mx1, 1));
            mx1 = fmaxf(mx1, __shfl_xor_sync(0xffffffffu, mx1, 2));
            const float mn0 = fmaxf(m0, mx0), mn1 = fmaxf(m1, mx1);
            const float al0 = __expf(m0 - mn0), al1 = __expf(m1 - mn1);
            float s0 = 0.f, s1 = 0.f;
            uint32_t Pa[8], Pb[8];
            #pragma unroll
            for (int nt = 0; nt < 8; nt++) {
                float p0 = __expf(S[nt][0] - mn0);
                float p1 = __expf(S[nt][1] - mn0);
                float p2 = __expf(S[nt][2] - mn1);
                float p3 = __expf(S[nt][3] - mn1);
                s0 += p0 + p1; s1 += p2 + p3;
                Pa[nt] = pack2f(p0, p1);
                Pb[nt] = pack2f(p2, p3);
            }
            s0 += __shfl_xor_sync(0xffffffffu, s0, 1);
            s0 += __shfl_xor_sync(0xffffffffu, s0, 2);
            s1 += __shfl_xor_sync(0xffffffffu, s1, 1);
            s1 += __shfl_xor_sync(0xffffffffu, s1, 2);
            l0 = l0 * al0 + s0; l1 = l1 * al1 + s1;
            m0 = mn0; m1 = mn1;
            #pragma unroll
            for (int nt = 0; nt < 8; nt++) {
                Oacc[nt][0] *= al0; Oacc[nt][1] *= al0;
                Oacc[nt][2] *= al1; Oacc[nt][3] *= al1;
            }

            #pragma unroll
            for (int ks = 0; ks < 4; ks++) {
                const int koff = ks * 8 + 2 * q;
                uint32_t af[4] = {Pa[2 * ks], Pb[2 * ks], Pa[2 * ks + 1], Pb[2 * ks + 1]};
                #pragma unroll
                for (int nt = 0; nt < 8; nt++) {
                    uint2 b = *(const uint2*)&Vb[(nt * 8 + r) * AP + koff];
                    mma_f16(Oacc[nt], af, b.x, b.y);
                }
            }
        }
        __syncthreads();
    }

    const float li0 = 1.f / l0, li1 = 1.f / l1;
    const int b = bh / H_;
    const int h = bh - b * H_;
    const int row0 = qt * 128 + wrow + r;
    const int row1 = row0 + 8;
    uint32_t* o0 = g_atth + (size_t)(b * T_ + row0) * KP2 + h * 32;
    uint32_t* o1 = g_atth + (size_t)(b * T_ + row1) * KP2 + h * 32;
    #pragma unroll
    for (int nt = 0; nt < 8; nt++) {
        const int slot = (nt >> 1) * 8 + (q << 1) + (nt & 1);
        o0[slot] = pack2f(Oacc[nt][0] * li0, Oacc[nt][1] * li0);
        o1[slot] = pack2f(Oacc[nt][2] * li1, Oacc[nt][3] * li1);
    }
}

// ---------------------------------------------------------------------------
extern "C" void kernel_launch(void* const* d_in, const int* in_sizes, int n_in,
                              void* d_out, int out_size) {
    const float* x     = (const float*)d_in[0];
    const float* Wqkv  = (const float*)d_in[1];
    const float* bqkv  = (const float*)d_in[2];
    const float* Wproj = (const float*)d_in[3];
    const float* bproj = (const float*)d_in[4];
    float* out = (float*)d_out;

    cudaFuncSetAttribute(gemm_h<3 * C_, 0>, cudaFuncAttributeMaxDynamicSharedMemorySize, GEMM_SMEM);
    cudaFuncSetAttribute(gemm_h<C_, 1>,     cudaFuncAttributeMaxDynamicSharedMemorySize, GEMM_SMEM);
    cudaFuncSetAttribute(attn_h,            cudaFuncAttributeMaxDynamicSharedMemorySize, ATT_SMEM);

    // 0) fused conversions (x + both weight transposes in one launch)
    conv_in<<<CONVX_BLOCKS + 576, 256>>>(x, Wqkv, Wproj);

    // 1) QKV projection -> q/k slotted + V transposed in-epilogue
    gemm_h<3 * C_, 0><<<dim3(3 * C_ / 64, M_TOT / 128), 256, GEMM_SMEM>>>(bqkv, nullptr);

    // 2) causal flash attention (fp16 tensor cores, register P)
    attn_h<<<dim3(T_ / 128, B_ * H_), 256, ATT_SMEM>>>();

    // 3) output projection
    gemm_h<C_, 1><<<dim3(C_ / 64, M_TOT / 128), 256, GEMM_SMEM>>>(bproj, out);
}

// round 16
// speedup vs baseline: 1.1370x; 1.0448x over previous
#include <cuda_runtime.h>
#include <cuda_fp16.h>
#include <math.h>
#include <cstdint>

#define B_ 64
#define T_ 256
#define C_ 384
#define H_ 6
#define D_ 64
#define K_ 384
#define M_TOT (B_*T_)   // 16384
#define KP2 (K_/2)      // 192 u32 (half2) per row

// ------------------------- scratch (no allocation) -------------------------
__device__ uint32_t g_xh[M_TOT*KP2];        // x, fp16 pairs, pair-slotted
__device__ uint32_t g_wqh[3*C_*KP2];        // Wqkv^T [n][pair-slot(k)]
__device__ uint32_t g_wph[C_*KP2];          // Wproj^T
__device__ uint32_t g_atth[M_TOT*KP2];      // attention out, fp16 slotted
__device__ uint32_t g_qh[B_*H_*T_*(D_/2)];  // [b,h,t][d-pair slot]
__device__ uint32_t g_kh[B_*H_*T_*(D_/2)];
__device__ uint32_t g_vt[B_*H_*D_*(T_/2)];  // V^T: [b,h,d][key-pair slot]

// ------------------------- helpers -------------------------
__device__ __forceinline__ int slot8(int p) { return (p & ~7) | (((p & 3) << 1) | ((p >> 2) & 1)); }

__device__ __forceinline__ uint32_t pack2f(float a, float b) {
    __half2 h = __floats2half2_rn(a, b);
    return *reinterpret_cast<uint32_t*>(&h);
}
__device__ __forceinline__ void mma_f16(float c[4], const uint32_t a[4], uint32_t b0, uint32_t b1) {
    asm volatile(
        "mma.sync.aligned.m16n8k16.row.col.f32.f16.f16.f32 "
        "{%0,%1,%2,%3}, {%4,%5,%6,%7}, {%8,%9}, {%0,%1,%2,%3};"
        : "+f"(c[0]), "+f"(c[1]), "+f"(c[2]), "+f"(c[3])
        : "r"(a[0]), "r"(a[1]), "r"(a[2]), "r"(a[3]), "r"(b0), "r"(b1));
}
#define CP16(dst, src) asm volatile("cp.async.cg.shared.global [%0], [%1], 16;" :: "r"(dst), "l"(src) : "memory")
#define CP_COMMIT()    asm volatile("cp.async.commit_group;" ::: "memory")
#define CP_WAIT1()     asm volatile("cp.async.wait_group 1;" ::: "memory")
#define CP_WAIT0()     asm volatile("cp.async.wait_group 0;" ::: "memory")
__device__ __forceinline__ uint32_t smem_u32(const void* p) {
    uint32_t a;
    asm("{ .reg .u64 t; cvta.to.shared.u64 t, %1; cvt.u32.u64 %0, t; }" : "=r"(a) : "l"(p));
    return a;
}

// ------------------------- merged conversion kernel -------------------------
// blocks [0,1536): x -> g_xh (16 floats / thread, slotted half2)
// blocks [1536,2112): W transpose -> g_wqh / g_wph
#define CONVX_BLOCKS (M_TOT * K_ / 16 / 256)   // 1536
__global__ __launch_bounds__(256) void conv_in(const float* __restrict__ x,
                                               const float* __restrict__ Wq,
                                               const float* __restrict__ Wp) {
    __shared__ float t[32][33];
    const int bx = blockIdx.x;
    const int tid = threadIdx.x;
    if (bx < CONVX_BLOCKS) {
        const int gi = bx * 256 + tid;
        const float* s = x + (size_t)gi * 16;
        float4 v0 = *(const float4*)(s);
        float4 v1 = *(const float4*)(s + 4);
        float4 v2 = *(const float4*)(s + 8);
        float4 v3 = *(const float4*)(s + 12);
        uint32_t* o = g_xh + (size_t)gi * 8;
        o[0] = pack2f(v0.x, v0.y); o[2] = pack2f(v0.z, v0.w);
        o[4] = pack2f(v1.x, v1.y); o[6] = pack2f(v1.z, v1.w);
        o[1] = pack2f(v2.x, v2.y); o[3] = pack2f(v2.z, v2.w);
        o[5] = pack2f(v3.x, v3.y); o[7] = pack2f(v3.z, v3.w);
    } else {
        const int idx = bx - CONVX_BLOCKS;     // 0..575
        const int wbx = idx % 48;              // n-tile
        const int ky = idx / 48;               // k-tile (0..11)
        const bool isq = wbx < 36;
        const float* W = isq ? Wq : Wp;
        uint32_t* out = isq ? g_wqh : g_wph;
        const int N = isq ? 1152 : 384;
        const int nx = (isq ? wbx : wbx - 36) * 32;
        const int kx = ky * 32;
        const int xi = tid & 31, yi = tid >> 5;
        #pragma unroll
        for (int i = yi; i < 32; i += 8) t[i][xi] = W[(size_t)(kx + i) * N + nx + xi];
        __syncthreads();
        #pragma unroll
        for (int i = yi; i < 16; i += 8) {
            const int slot = slot8(i);
            out[(size_t)(nx + xi) * KP2 + kx / 2 + slot] = pack2f(t[2 * i][xi], t[2 * i + 1][xi]);
        }
    }
}

// ---------------------------------------------------------------------------
// QKV fp16 MMA GEMM. Block 128(M)x64(N), BK=32, 256 threads, 8 warps 4x2,
// warp tile 32x32. Fully-unrolled 12-chunk k-loop. occ-3 config (measured best).
// Epilogue: q/k slotted; V transposed IN-REGISTER (shfl) -> g_vt.
// ---------------------------------------------------------------------------
#define GP 24
#define STG (192 * GP * 4)       // 18432 B/stage
#define GEMM_SMEM (3 * STG)      // 55296

__global__ __launch_bounds__(256, 3) void gemm_qkv(const float* __restrict__ bias) {
    extern __shared__ char smem[];
    const uint32_t sb = smem_u32(smem);
    const uint32_t* sm = (const uint32_t*)smem;

    const int tid = threadIdx.x;
    const int wid = tid >> 5;
    const int lane = tid & 31;
    const int r = lane >> 2, q = lane & 3;
    const int m0 = blockIdx.y * 128;
    const int n0 = blockIdx.x * 64;
    const int wm = (wid & 3) * 32;
    const int wn = (wid >> 2) * 32;

    const uint32_t* Ap = g_xh;
    const uint32_t* Bp = g_wqh;

    const int c0 = tid,        row0l = c0 >> 2, seg0 = c0 & 3;
    const int c1 = tid + 256,  row1l = c1 >> 2, seg1 = c1 & 3;
    const int c2 = tid + 512,  row2l = c2 >> 2, seg2 = c2 & 3;
    const uint32_t* src0 = Ap + (size_t)(m0 + row0l) * KP2 + seg0 * 4;
    const uint32_t* src1 = (row1l < 128)
        ? Ap + (size_t)(m0 + row1l) * KP2 + seg1 * 4
        : Bp + (size_t)(n0 + row1l - 128) * KP2 + seg1 * 4;
    const uint32_t* src2 = Bp + (size_t)(n0 + row2l - 128) * KP2 + seg2 * 4;
    const uint32_t d0 = sb + row0l * (GP * 4) + seg0 * 16;
    const uint32_t d1 = sb + row1l * (GP * 4) + seg1 * 16;
    const uint32_t d2 = sb + row2l * (GP * 4) + seg2 * 16;

    auto load_stage = [&](int kc, int st) {
        const int ko = kc * 16;
        CP16(d0 + st * STG, src0 + ko);
        CP16(d1 + st * STG, src1 + ko);
        CP16(d2 + st * STG, src2 + ko);
        CP_COMMIT();
    };

    float acc[2][4][4] = {};
    load_stage(0, 0);
    load_stage(1, 1);

    const int NCH = K_ / 32;   // 12
    #pragma unroll
    for (int kc = 0; kc < NCH; kc++) {
        const int st = kc % 3;
        if (kc < NCH - 1) CP_WAIT1(); else CP_WAIT0();
        __syncthreads();
        if (kc + 2 < NCH) load_stage(kc + 2, (kc + 2) % 3);

        const uint32_t* As = sm + st * (STG / 4);
        const uint32_t* Bs = As + 128 * GP;
        #pragma unroll
        for (int ks = 0; ks < 2; ks++) {
            const int koff = ks * 8 + 2 * q;
            uint32_t af[2][4];
            #pragma unroll
            for (int mt = 0; mt < 2; mt++) {
                const int mr = wm + mt * 16 + r;
                uint2 a0 = *(const uint2*)&As[mr * GP + koff];
                uint2 a1 = *(const uint2*)&As[(mr + 8) * GP + koff];
                af[mt][0] = a0.x; af[mt][1] = a1.x; af[mt][2] = a0.y; af[mt][3] = a1.y;
            }
            uint2 bf[4];
            #pragma unroll
            for (int nt = 0; nt < 4; nt++)
                bf[nt] = *(const uint2*)&Bs[(wn + nt * 8 + r) * GP + koff];
            #pragma unroll
            for (int mt = 0; mt < 2; mt++)
                #pragma unroll
                for (int nt = 0; nt < 4; nt++)
                    mma_f16(acc[mt][nt], af[mt], bf[nt].x, bf[nt].y);
        }
    }

    // ---- epilogue: q/k slotted, V transposed in-register ----
    #pragma unroll
    for (int mt = 0; mt < 2; mt++) {
        #pragma unroll
        for (int nt = 0; nt < 4; nt++) {
            const int row0 = m0 + wm + mt * 16 + r;
            const int row1 = row0 + 8;
            const int col = n0 + wn + nt * 8 + q * 2;
            const float b0 = bias[col], b1 = bias[col + 1];
            const float v00 = acc[mt][nt][0] + b0, v01 = acc[mt][nt][1] + b1;
            const float v10 = acc[mt][nt][2] + b0, v11 = acc[mt][nt][3] + b1;
            const int which = n0 / C_;
            const int rem = col - which * C_;
            const int h = rem >> 6, d = rem & 63;
            const int b0i = row0 >> 8;
            if (which < 2) {
                const int slot = slot8(d >> 1);
                uint32_t* qkv = (which == 0) ? g_qh : g_kh;
                const int t0 = row0 & 255;
                const int t1 = row1 & 255;
                qkv[((size_t)(b0i * H_ + h) * T_ + t0) * 32 + slot] = pack2f(v00, v01);
                qkv[((size_t)(b0i * H_ + h) * T_ + t1) * 32 + slot] = pack2f(v10, v11);
            } else {
                const float p00 = __shfl_xor_sync(0xffffffffu, v00, 4);
                const float p01 = __shfl_xor_sync(0xffffffffu, v01, 4);
                const float p10 = __shfl_xor_sync(0xffffffffu, v10, 4);
                const float p11 = __shfl_xor_sync(0xffffffffu, v11, 4);
                if (!(r & 1)) {
                    const int t0 = row0 & 255;
                    const int t1 = row1 & 255;
                    const int s0 = slot8(t0 >> 1);
                    const int s1 = slot8(t1 >> 1);
                    uint32_t* vt = g_vt + (size_t)(b0i * H_ + h) * 64 * (T_ / 2);
                    vt[(size_t)d * (T_ / 2) + s0]       = pack2f(v00, p00);
                    vt[(size_t)(d + 1) * (T_ / 2) + s0] = pack2f(v01, p01);
                    vt[(size_t)d * (T_ / 2) + s1]       = pack2f(v10, p10);
                    vt[(size_t)(d + 1) * (T_ / 2) + s1] = pack2f(v11, p11);
                }
            }
        }
    }
}

// ---------------------------------------------------------------------------
// Proj fp16 MMA GEMM. Block 128(M)x128(N), BK=32, 256 threads, 8 warps 2x4,
// warp tile 64x32 (2x better smem reuse). A re-read 3x (was 6x). 2 CTAs/SM.
// ---------------------------------------------------------------------------
#define PSTG (256 * GP * 4)       // 24576 B/stage (A 128 rows + B 128 rows)
#define PROJ_SMEM (3 * PSTG)      // 73728

__global__ __launch_bounds__(256, 2) void gemm_proj(const float* __restrict__ bias,
                                                    float* __restrict__ out) {
    extern __shared__ char smem[];
    const uint32_t sb = smem_u32(smem);
    const uint32_t* sm = (const uint32_t*)smem;

    const int tid = threadIdx.x;
    const int wid = tid >> 5;
    const int lane = tid & 31;
    const int r = lane >> 2, q = lane & 3;
    const int m0 = blockIdx.y * 128;
    const int n0 = blockIdx.x * 128;
    const int wm = (wid & 1) * 64;
    const int wn = (wid >> 1) * 32;

    const uint32_t* Ap = g_atth;
    const uint32_t* Bp = g_wph;

    auto load_stage = [&](int kc, int st) {
        #pragma unroll
        for (int j = 0; j < 4; j++) {
            const int c = tid + j * 256;
            const int row = c >> 2, seg = c & 3;
            const uint32_t* src = (row < 128)
                ? Ap + (size_t)(m0 + row) * KP2 + kc * 16 + seg * 4
                : Bp + (size_t)(n0 + row - 128) * KP2 + kc * 16 + seg * 4;
            CP16(sb + st * PSTG + row * (GP * 4) + seg * 16, src);
        }
        CP_COMMIT();
    };

    float acc[4][4][4] = {};
    load_stage(0, 0);
    load_stage(1, 1);

    const int NCH = K_ / 32;   // 12
    #pragma unroll
    for (int kc = 0; kc < NCH; kc++) {
        const int st = kc % 3;
        if (kc < NCH - 1) CP_WAIT1(); else CP_WAIT0();
        __syncthreads();
        if (kc + 2 < NCH) load_stage(kc + 2, (kc + 2) % 3);

        const uint32_t* As = sm + st * (PSTG / 4);
        const uint32_t* Bs = As + 128 * GP;
        #pragma unroll
        for (int ks = 0; ks < 2; ks++) {
            const int koff = ks * 8 + 2 * q;
            uint32_t af[4][4];
            #pragma unroll
            for (int mt = 0; mt < 4; mt++) {
                const int mr = wm + mt * 16 + r;
                uint2 a0 = *(const uint2*)&As[mr * GP + koff];
                uint2 a1 = *(const uint2*)&As[(mr + 8) * GP + koff];
                af[mt][0] = a0.x; af[mt][1] = a1.x; af[mt][2] = a0.y; af[mt][3] = a1.y;
            }
            uint2 bf[4];
            #pragma unroll
            for (int nt = 0; nt < 4; nt++)
                bf[nt] = *(const uint2*)&Bs[(wn + nt * 8 + r) * GP + koff];
            #pragma unroll
            for (int mt = 0; mt < 4; mt++)
                #pragma unroll
                for (int nt = 0; nt < 4; nt++)
                    mma_f16(acc[mt][nt], af[mt], bf[nt].x, bf[nt].y);
        }
    }

    // ---- epilogue ----
    #pragma unroll
    for (int mt = 0; mt < 4; mt++) {
        #pragma unroll
        for (int nt = 0; nt < 4; nt++) {
            const int row0 = m0 + wm + mt * 16 + r;
            const int row1 = row0 + 8;
            const int col = n0 + wn + nt * 8 + q * 2;
            const float b0 = bias[col], b1 = bias[col + 1];
            *(float2*)&out[(size_t)row0 * C_ + col] =
                make_float2(acc[mt][nt][0] + b0, acc[mt][nt][1] + b1);
            *(float2*)&out[(size_t)row1 * C_ + col] =
                make_float2(acc[mt][nt][2] + b0, acc[mt][nt][3] + b1);
        }
    }
}

// ---------------------------------------------------------------------------
// Flash attention, fp16 mma (unchanged from round-14 passing kernel).
// Br=128, Bc=64, 256 threads. Double-buffered K/V; register-resident P.
// smem (u32, pitch 40): Q[128] @0, K[2][64] @5120, V[2][64] @10240
// ---------------------------------------------------------------------------
#define AP 40
#define ATT_SMEM 61440

__global__ __launch_bounds__(256) void attn_h() {
    extern __shared__ uint32_t dsm[];
    uint32_t* Qs = dsm;            // 128 x 40

    const int tid = threadIdx.x;
    const int w = tid >> 5;
    const int lane = tid & 31;
    const int r = lane >> 2, q = lane & 3;
    const int qt = blockIdx.x;     // 0..1
    const int bh = blockIdx.y;
    const int wrow = w * 16;

    const uint32_t sbase = smem_u32(dsm);
    const uint32_t sQ = sbase;
    const uint32_t sK = sbase + 20480;
    const uint32_t sV = sbase + 40960;

    {
        const uint32_t* src = g_qh + (size_t)(bh * T_ + qt * 128) * 32;
        #pragma unroll
        for (int j = 0; j < 4; j++) {
            const int c = tid + j * 256;
            const int row = c >> 3, seg = c & 7;
            CP16(sQ + row * (AP * 4) + seg * 16, src + row * 32 + seg * 4);
        }
        CP_COMMIT();
    }

    auto load_kv = [&](int jt, int buf) {
        const uint32_t* ksrc = g_kh + (size_t)(bh * T_ + jt * 64) * 32;
        const uint32_t* vsrc = g_vt + (size_t)bh * 64 * (T_ / 2) + jt * 32;
        #pragma unroll
        for (int j = 0; j < 2; j++) {
            const int c = tid + j * 256;
            const int row = c >> 3, seg = c & 7;
            CP16(sK + buf * 10240 + row * (AP * 4) + seg * 16, ksrc + row * 32 + seg * 4);
            CP16(sV + buf * 10240 + row * (AP * 4) + seg * 16, vsrc + (size_t)row * (T_ / 2) + seg * 4);
        }
        CP_COMMIT();
    };
    load_kv(0, 0);

    float m0 = -INFINITY, m1 = -INFINITY, l0 = 0.f, l1 = 0.f;
    float Oacc[8][4] = {};

    const int nkt = 2 * (qt + 1);
    for (int jt = 0; jt < nkt; jt++) {
        if (jt + 1 < nkt) load_kv(jt + 1, (jt + 1) & 1);
        if (jt + 1 < nkt) CP_WAIT1(); else CP_WAIT0();
        __syncthreads();

        if (qt * 128 + wrow + 15 >= jt * 64) {
            const uint32_t* Kb = dsm + 5120 + (jt & 1) * 2560;
            const uint32_t* Vb = dsm + 10240 + (jt & 1) * 2560;

            float S[8][4] = {};
            #pragma unroll
            for (int ks = 0; ks < 4; ks++) {
                const int koff = ks * 8 + 2 * q;
                uint2 a0 = *(const uint2*)&Qs[(wrow + r) * AP + koff];
                uint2 a1 = *(const uint2*)&Qs[(wrow + r + 8) * AP + koff];
                uint32_t af[4] = {a0.x, a1.x, a0.y, a1.y};
                #pragma unroll
                for (int nt = 0; nt < 8; nt++) {
                    uint2 b = *(const uint2*)&Kb[(nt * 8 + r) * AP + koff];
                    mma_f16(S[nt], af, b.x, b.y);
                }
            }

            #pragma unroll
            for (int nt = 0; nt < 8; nt++)
                #pragma unroll
                for (int c = 0; c < 4; c++)
                    S[nt][c] *= 0.125f;

            if (jt * 64 + 63 > qt * 128 + wrow) {
                const int ir0 = qt * 128 + wrow + r;
                const int ir1 = ir0 + 8;
                #pragma unroll
                for (int nt = 0; nt < 8; nt++) {
                    const int jc = jt * 64 + nt * 8 + 2 * q;
                    if (jc > ir0)     S[nt][0] = -INFINITY;
                    if (jc + 1 > ir0) S[nt][1] = -INFINITY;
                    if (jc > ir1)     S[nt][2] = -INFINITY;
                    if (jc + 1 > ir1) S[nt][3] = -INFINITY;
                }
            }

            float mx0 = -INFINITY, mx1 = -INFINITY;
            #pragma unroll
            for (int nt = 0; nt < 8; nt++) {
                mx0 = fmaxf(mx0, fmaxf(S[nt][0], S[nt][1]));
                mx1 = fmaxf(mx1, fmaxf(S[nt][2], S[nt][3]));
            }
            mx0 = fmaxf(mx0, __shfl_xor_sync(0xffffffffu, mx0, 1));
            mx0 = fmaxf(mx0, __shfl_xor_sync(0xffffffffu, mx0, 2));
            mx1 = fmaxf(mx1, __shfl_xor_sync(0xffffffffu, mx1, 1));
            mx1 = fmaxf(mx1, __shfl_xor_sync(0xffffffffu, mx1, 2));
            const float mn0 = fmaxf(m0, mx0), mn1 = fmaxf(m1, mx1);
            const float al0 = __expf(m0 - mn0), al1 = __expf(m1 - mn1);
            float s0 = 0.f, s1 = 0.f;
            uint32_t Pa[8], Pb[8];
            #pragma unroll
            for (int nt = 0; nt < 8; nt++) {
                float p0 = __expf(S[nt][0] - mn0);
                float p1 = __expf(S[nt][1] - mn0);
                float p2 = __expf(S[nt][2] - mn1);
                float p3 = __expf(S[nt][3] - mn1);
                s0 += p0 + p1; s1 += p2 + p3;
                Pa[nt] = pack2f(p0, p1);
                Pb[nt] = pack2f(p2, p3);
            }
            s0 += __shfl_xor_sync(0xffffffffu, s0, 1);
            s0 += __shfl_xor_sync(0xffffffffu, s0, 2);
            s1 += __shfl_xor_sync(0xffffffffu, s1, 1);
            s1 += __shfl_xor_sync(0xffffffffu, s1, 2);
            l0 = l0 * al0 + s0; l1 = l1 * al1 + s1;
            m0 = mn0; m1 = mn1;
            #pragma unroll
            for (int nt = 0; nt < 8; nt++) {
                Oacc[nt][0] *= al0; Oacc[nt][1] *= al0;
                Oacc[nt][2] *= al1; Oacc[nt][3] *= al1;
            }

            #pragma unroll
            for (int ks = 0; ks < 4; ks++) {
                const int koff = ks * 8 + 2 * q;
                uint32_t af[4] = {Pa[2 * ks], Pb[2 * ks], Pa[2 * ks + 1], Pb[2 * ks + 1]};
                #pragma unroll
                for (int nt = 0; nt < 8; nt++) {
                    uint2 b = *(const uint2*)&Vb[(nt * 8 + r) * AP + koff];
                    mma_f16(Oacc[nt], af, b.x, b.y);
                }
            }
        }
        __syncthreads();
    }

    const float li0 = 1.f / l0, li1 = 1.f / l1;
    const int b = bh / H_;
    const int h = bh - b * H_;
    const int row0 = qt * 128 + wrow + r;
    const int row1 = row0 + 8;
    uint32_t* o0 = g_atth + (size_t)(b * T_ + row0) * KP2 + h * 32;
    uint32_t* o1 = g_atth + (size_t)(b * T_ + row1) * KP2 + h * 32;
    #pragma unroll
    for (int nt = 0; nt < 8; nt++) {
        const int slot = (nt >> 1) * 8 + (q << 1) + (nt & 1);
        o0[slot] = pack2f(Oacc[nt][0] * li0, Oacc[nt][1] * li0);
        o1[slot] = pack2f(Oacc[nt][2] * li1, Oacc[nt][3] * li1);
    }
}

// ---------------------------------------------------------------------------
extern "C" void kernel_launch(void* const* d_in, const int* in_sizes, int n_in,
                              void* d_out, int out_size) {
    const float* x     = (const float*)d_in[0];
    const float* Wqkv  = (const float*)d_in[1];
    const float* bqkv  = (const float*)d_in[2];
    const float* Wproj = (const float*)d_in[3];
    const float* bproj = (const float*)d_in[4];
    float* out = (float*)d_out;

    cudaFuncSetAttribute(gemm_qkv,  cudaFuncAttributeMaxDynamicSharedMemorySize, GEMM_SMEM);
    cudaFuncSetAttribute(gemm_proj, cudaFuncAttributeMaxDynamicSharedMemorySize, PROJ_SMEM);
    cudaFuncSetAttribute(attn_h,    cudaFuncAttributeMaxDynamicSharedMemorySize, ATT_SMEM);

    // 0) fused conversions (x + both weight transposes in one launch)
    conv_in<<<CONVX_BLOCKS + 576, 256>>>(x, Wqkv, Wproj);

    // 1) QKV projection -> q/k slotted + V transposed in-epilogue
    gemm_qkv<<<dim3(3 * C_ / 64, M_TOT / 128), 256, GEMM_SMEM>>>(bqkv);

    // 2) causal flash attention (fp16 tensor cores, register P)
    attn_h<<<dim3(T_ / 128, B_ * H_), 256, ATT_SMEM>>>();

    // 3) output projection (128x128 tile, 2x smem reuse)
    gemm_proj<<<dim3(C_ / 128, M_TOT / 128), 256, PROJ_SMEM>>>(bproj, out);
}